// round 1
// baseline (speedup 1.0000x reference)
#include <cuda_runtime.h>

// Problem constants (fixed by the dataset)
#define NN      100000      // nodes
#define DIN     256         // input feature dim
#define DOUT    32          // output feature dim
#define KC      64          // K-chunk for GEMM shared tile
#define RPB     128         // rows per GEMM block
#define XS_STRIDE (KC + 4)  // padded (16B-aligned) row stride for Xs

// Scratch for pre_sup = x @ W  [NN, DOUT] (12.8 MB, device global per rules)
__device__ float g_presup[(size_t)NN * DOUT];

// ---------------------------------------------------------------------------
// Kernel 1: GEMM  pre_sup[N, 32] = x[N, 256] @ W[256, 32]
// 128 threads/block, block covers 128 rows x 32 cols.
// Thread (tc = tid&7, tr = tid>>3) computes an 8-row x 4-col register tile.
// ---------------------------------------------------------------------------
__global__ __launch_bounds__(128) void gemm_kernel(const float* __restrict__ x,
                                                   const float* __restrict__ w) {
    __shared__ float Ws[KC * DOUT];          // 8 KB  (current K-chunk of W)
    __shared__ float Xs[RPB * XS_STRIDE];    // 34 KB (128-row x 64-col x tile)

    const int tid  = threadIdx.x;
    const int row0 = blockIdx.x * RPB;
    const int tc   = tid & 7;    // -> cols  tc*4 .. tc*4+3
    const int tr   = tid >> 3;   // -> rows  tr*8 .. tr*8+7

    float acc[8][4];
#pragma unroll
    for (int r = 0; r < 8; r++)
#pragma unroll
        for (int c = 0; c < 4; c++) acc[r][c] = 0.f;

    for (int kc = 0; kc < DIN; kc += KC) {
        __syncthreads();
        // Load W chunk [KC, 32]: 512 float4 across 128 threads
        {
            const float4* wsrc = (const float4*)(w + (size_t)kc * DOUT);
#pragma unroll
            for (int i = 0; i < (KC * DOUT / 4) / 128; i++)
                ((float4*)Ws)[tid + i * 128] = wsrc[tid + i * 128];
        }
        // Load X tile [128, KC]: 2048 float4 across 128 threads (coalesced 256B runs)
#pragma unroll
        for (int i = 0; i < (RPB * KC / 4) / 128; i++) {
            int s   = tid + i * 128;
            int r   = s >> 4;        // 16 float4 per row
            int c4  = s & 15;
            int grow = row0 + r;
            float4 v = make_float4(0.f, 0.f, 0.f, 0.f);
            if (grow < NN)
                v = *(const float4*)(x + (size_t)grow * DIN + kc + c4 * 4);
            *(float4*)(Xs + r * XS_STRIDE + c4 * 4) = v;
        }
        __syncthreads();

#pragma unroll 8
        for (int k = 0; k < KC; k++) {
            float4 w4 = *(const float4*)(Ws + k * DOUT + tc * 4);
#pragma unroll
            for (int r = 0; r < 8; r++) {
                float xv = Xs[(tr * 8 + r) * XS_STRIDE + k];
                acc[r][0] = fmaf(xv, w4.x, acc[r][0]);
                acc[r][1] = fmaf(xv, w4.y, acc[r][1]);
                acc[r][2] = fmaf(xv, w4.z, acc[r][2]);
                acc[r][3] = fmaf(xv, w4.w, acc[r][3]);
            }
        }
    }

#pragma unroll
    for (int r = 0; r < 8; r++) {
        int grow = row0 + tr * 8 + r;
        if (grow < NN) {
            float4 o = make_float4(acc[r][0], acc[r][1], acc[r][2], acc[r][3]);
            *(float4*)(g_presup + (size_t)grow * DOUT + tc * 4) = o;
        }
    }
}

// ---------------------------------------------------------------------------
// Kernel 2: Scatter SpMM  out[row[e]] += val[e] * pre_sup[col[e]]
// 8 threads per edge; each handles 4 columns via one float4 gather +
// one red.global.add.v4.f32 (sm_90+ vector reduction, no return).
// ---------------------------------------------------------------------------
__global__ __launch_bounds__(256) void scatter_kernel(const int*   __restrict__ arow,
                                                      const int*   __restrict__ acol,
                                                      const float* __restrict__ aval,
                                                      float*       __restrict__ out,
                                                      int n_edges) {
    long long g = (long long)blockIdx.x * blockDim.x + threadIdx.x;
    int e    = (int)(g >> 3);
    int part = (int)(g & 7);
    if (e >= n_edges) return;

    int   r = arow[e];
    int   c = acol[e];
    float v = aval[e];

    float4 p = *(const float4*)(g_presup + (size_t)c * DOUT + part * 4);
    float m0 = v * p.x, m1 = v * p.y, m2 = v * p.z, m3 = v * p.w;

    float* dst = out + (size_t)r * DOUT + part * 4;
    asm volatile("red.global.add.v4.f32 [%0], {%1, %2, %3, %4};"
                 :: "l"(dst), "f"(m0), "f"(m1), "f"(m2), "f"(m3)
                 : "memory");
}

// ---------------------------------------------------------------------------
// Kernel 3: in-place ReLU on out (after all reductions complete)
// ---------------------------------------------------------------------------
__global__ __launch_bounds__(256) void relu_kernel(float* __restrict__ out, int n4) {
    int i = blockIdx.x * blockDim.x + threadIdx.x;
    if (i < n4) {
        float4 v = ((float4*)out)[i];
        v.x = fmaxf(v.x, 0.f);
        v.y = fmaxf(v.y, 0.f);
        v.z = fmaxf(v.z, 0.f);
        v.w = fmaxf(v.w, 0.f);
        ((float4*)out)[i] = v;
    }
}

// ---------------------------------------------------------------------------
// kernel_launch: memset(out) -> gemm -> scatter -> relu   (all graph-capturable)
// Inputs (metadata order): x[N*256] f32, adj_row[E] i32, adj_col[E] i32,
//                          adj_val[E] f32, weight[256*32] f32. Output f32 [N*32].
// ---------------------------------------------------------------------------
extern "C" void kernel_launch(void* const* d_in, const int* in_sizes, int n_in,
                              void* d_out, int out_size) {
    const float* x    = (const float*)d_in[0];
    const int*   arow = (const int*)  d_in[1];
    const int*   acol = (const int*)  d_in[2];
    const float* aval = (const float*)d_in[3];
    const float* w    = (const float*)d_in[4];
    float*       out  = (float*)d_out;

    const int n_edges = in_sizes[1];

    cudaMemsetAsync(out, 0, (size_t)out_size * sizeof(float), 0);

    gemm_kernel<<<(NN + RPB - 1) / RPB, 128>>>(x, w);

    long long sthreads = (long long)n_edges * 8;
    int sblocks = (int)((sthreads + 255) / 256);
    scatter_kernel<<<sblocks, 256>>>(arow, acol, aval, out, n_edges);

    int n4 = out_size / 4;
    relu_kernel<<<(n4 + 255) / 256, 256>>>(out, n4);
}